// round 4
// baseline (speedup 1.0000x reference)
#include <cuda_runtime.h>
#include <math.h>

// ---------------------------------------------------------------------------
// Compile-time DCT-II matrix (matches reference: PI = 3.1415926 truncated).
// All 64 entries are +/- one of 8 magnitudes: 0.5*cos(k*pi/16), k=0..7,
// and row 0 = sqrt(1/8). Folding error vs float64-built reference < 4e-7.
// Instantiated as a function-local constexpr in each kernel so every
// CD.v[const][const] folds to an FFMA immediate (no LDS/LDC, no
// --expt-relaxed-constexpr needed).
// ---------------------------------------------------------------------------
struct DCTTab { float v[8][8]; };

__host__ __device__ constexpr DCTTab make_dct() {
    // ck[a] = 0.5 * cos(a*pi/16)
    const float ck[9] = {0.5f,        0.49039264f, 0.46193977f, 0.41573481f,
                         0.35355339f, 0.27778512f, 0.19134172f, 0.09754516f,
                         0.0f};
    DCTTab t{};
    for (int i = 0; i < 8; i++) {
        for (int j = 0; j < 8; j++) {
            if (i == 0) { t.v[i][j] = 0.35355339f; continue; }  // sqrt(1/8)
            int a = (i * (2 * j + 1)) % 32;
            float s = 1.0f;
            if (a > 16) a = 32 - a;                  // cos(2pi - x) = cos(x)
            if (a > 8)  { a = 16 - a; s = -1.0f; }   // cos(pi - x) = -cos(x)
            t.v[i][j] = s * ck[a];
        }
    }
    return t;
}

// learned quant matrix, produced once per launch by the tiny setup kernel
__device__ float g_lq[64];

__device__ __forceinline__ float gelu_exact(float x) {
    return 0.5f * x * (1.0f + erff(x * 0.70710678f));
}

// ---------------------------------------------------------------------------
// Setup kernel: noise_level MLP -> nr[18]; softmax(qmat_weights);
// learned_qmat[h][w] = sum_i (softmax_i*nr0 + nr1)*nr[2+i] * qmat[i][h][w].
// 64 threads; MLP recomputed redundantly per thread (trivial cost).
// ---------------------------------------------------------------------------
__global__ void setup_kernel(const float* __restrict__ noise,
                             const float* __restrict__ qmat,
                             const float* __restrict__ qmw,
                             const float* __restrict__ w1, const float* __restrict__ b1,
                             const float* __restrict__ w2, const float* __restrict__ b2,
                             const float* __restrict__ w3, const float* __restrict__ b3) {
    int t = threadIdx.x;  // 0..63
    float nz = noise[0];

    float h1[16], h2[16];
#pragma unroll
    for (int k = 0; k < 16; k++) h1[k] = gelu_exact(nz * w1[k] + b1[k]);
#pragma unroll
    for (int k = 0; k < 16; k++) {
        float s = b2[k];
#pragma unroll
        for (int j = 0; j < 16; j++) s += h1[j] * w2[j * 16 + k];
        h2[k] = gelu_exact(s);
    }
    float nr[18];
#pragma unroll
    for (int k = 0; k < 18; k++) {
        float s = b3[k];
#pragma unroll
        for (int j = 0; j < 16; j++) s += h2[j] * w3[j * 18 + k];
        nr[k] = s;
    }

    // softmax over 16 qmat_weights
    float wmax = qmw[0];
#pragma unroll
    for (int i = 1; i < 16; i++) wmax = fmaxf(wmax, qmw[i]);
    float e[16], esum = 0.0f;
#pragma unroll
    for (int i = 0; i < 16; i++) { e[i] = expf(qmw[i] - wmax); esum += e[i]; }
    float inv = 1.0f / esum;

    float acc = 0.0f;
#pragma unroll
    for (int i = 0; i < 16; i++) {
        float coef = (e[i] * inv * nr[0] + nr[1]) * nr[2 + i];
        acc += coef * qmat[i * 64 + t];
    }
    g_lq[t] = acc;
}

// ---------------------------------------------------------------------------
// Main kernel: one CTA per 64x64 image (B*Ch = 8192 images), 512 threads.
// Each thread owns an 8-float segment in both orientations:
//   row phase : (r, bj) -> x[r][8bj..8bj+7]
//   col phase : (bi, c) -> Y[8bi..8bi+7][c]
// Pipeline: rowDCT -> smem -> colDCT, q-mask, colIDCT -> smem -> rowIDCT,
//           low = result, high = x - low (orthogonality identity).
// Pitch 65 + mapping r=(t&7)|((t>>6)<<3) makes every smem access
// conflict-free (verified bank math).
// ---------------------------------------------------------------------------
#define PITCH 65

__global__ void __launch_bounds__(512)
dct_kernel(const float* __restrict__ x,
           float* __restrict__ lo,
           float* __restrict__ hi) {
    constexpr DCTTab CD = make_dct();

    __shared__ float sY[64 * PITCH];
    __shared__ float sq[64];

    const int t = threadIdx.x;
    const long base = (long)blockIdx.x * 4096;

    if (t < 64) sq[t] = g_lq[t];

    // ---- Phase A: load + row DCT (X * C^T) ----
    const int r  = (t & 7) | ((t >> 6) << 3);  // 0..63
    const int bj = (t >> 3) & 7;               // 0..7
    const int cb = bj << 3;

    const float4* xp = reinterpret_cast<const float4*>(x + base + r * 64 + cb);
    float4 p0 = xp[0];
    float4 p1 = xp[1];
    float xv[8] = {p0.x, p0.y, p0.z, p0.w, p1.x, p1.y, p1.z, p1.w};

    float* yb = &sY[r * PITCH + cb];
#pragma unroll
    for (int m = 0; m < 8; m++) {
        float acc = 0.0f;
#pragma unroll
        for (int j = 0; j < 8; j++) acc = fmaf(xv[j], CD.v[m][j], acc);
        yb[m] = acc;
    }
    __syncthreads();

    // ---- Phase B: col DCT (C * Y), mask by q, col IDCT (C^T * F) ----
    {
        const int c  = t & 63;
        const int bi = t >> 6;
        const int m0 = c & 7;
        float* colp = &sY[(bi * 8) * PITCH + c];

        float v[8];
#pragma unroll
        for (int i = 0; i < 8; i++) v[i] = colp[i * PITCH];

        float ql[8];
#pragma unroll
        for (int i = 0; i < 8; i++) ql[i] = sq[i * 8 + m0];

        float f[8];
#pragma unroll
        for (int ip = 0; ip < 8; ip++) {
            float acc = 0.0f;
#pragma unroll
            for (int i = 0; i < 8; i++) acc = fmaf(v[i], CD.v[ip][i], acc);
            f[ip] = acc * ql[ip];
        }
#pragma unroll
        for (int a = 0; a < 8; a++) {
            float acc = 0.0f;
#pragma unroll
            for (int ip = 0; ip < 8; ip++) acc = fmaf(f[ip], CD.v[ip][a], acc);
            colp[a * PITCH] = acc;
        }
    }
    __syncthreads();

    // ---- Phase C: row IDCT (L1 * C), high = x - low, store ----
    float l[8];
#pragma unroll
    for (int m = 0; m < 8; m++) l[m] = yb[m];

    float lowv[8], highv[8];
#pragma unroll
    for (int b = 0; b < 8; b++) {
        float acc = 0.0f;
#pragma unroll
        for (int m = 0; m < 8; m++) acc = fmaf(l[m], CD.v[m][b], acc);
        lowv[b]  = acc;
        highv[b] = xv[b] - acc;
    }

    float4* lp = reinterpret_cast<float4*>(lo + base + r * 64 + cb);
    lp[0] = make_float4(lowv[0], lowv[1], lowv[2], lowv[3]);
    lp[1] = make_float4(lowv[4], lowv[5], lowv[6], lowv[7]);
    float4* hp = reinterpret_cast<float4*>(hi + base + r * 64 + cb);
    hp[0] = make_float4(highv[0], highv[1], highv[2], highv[3]);
    hp[1] = make_float4(highv[4], highv[5], highv[6], highv[7]);
}

// ---------------------------------------------------------------------------
// Launch: metadata order = x, noise_level, qmat, qmat_weights, w1,b1,w2,b2,w3,b3
// d_out = [low (N floats) | high (N floats)]
// ---------------------------------------------------------------------------
extern "C" void kernel_launch(void* const* d_in, const int* in_sizes, int n_in,
                              void* d_out, int out_size) {
    const float* x     = (const float*)d_in[0];
    const float* noise = (const float*)d_in[1];
    const float* qmat  = (const float*)d_in[2];
    const float* qmw   = (const float*)d_in[3];
    const float* w1    = (const float*)d_in[4];
    const float* b1    = (const float*)d_in[5];
    const float* w2    = (const float*)d_in[6];
    const float* b2    = (const float*)d_in[7];
    const float* w3    = (const float*)d_in[8];
    const float* b3    = (const float*)d_in[9];

    const int N    = in_sizes[0];     // 33554432
    const int nimg = N / 4096;        // 8192 images of 64x64

    float* lo = (float*)d_out;
    float* hi = lo + N;

    setup_kernel<<<1, 64>>>(noise, qmat, qmw, w1, b1, w2, b2, w3, b3);
    dct_kernel<<<nimg, 512>>>(x, lo, hi);
}

// round 7
// speedup vs baseline: 1.3434x; 1.3434x over previous
#include <cuda_runtime.h>
#include <math.h>

// ---------------------------------------------------------------------------
// Compile-time DCT-II matrix (matches reference: PI = 3.1415926 truncated).
// Entries are +/- 0.5*cos(k*pi/16) and sqrt(1/8); fold error vs reference
// < 4e-7. Function-local constexpr => every CD.v[const][const] becomes an
// FFMA immediate operand (imm-form FFMA, rt=1/SMSP; no LDS/LDC).
// ---------------------------------------------------------------------------
struct DCTTab { float v[8][8]; };

__host__ __device__ constexpr DCTTab make_dct() {
    const float ck[9] = {0.5f,        0.49039264f, 0.46193977f, 0.41573481f,
                         0.35355339f, 0.27778512f, 0.19134172f, 0.09754516f,
                         0.0f};
    DCTTab t{};
    for (int i = 0; i < 8; i++) {
        for (int j = 0; j < 8; j++) {
            if (i == 0) { t.v[i][j] = 0.35355339f; continue; }  // sqrt(1/8)
            int a = (i * (2 * j + 1)) % 32;
            float s = 1.0f;
            if (a > 16) a = 32 - a;                  // cos(2pi-x) =  cos(x)
            if (a > 8)  { a = 16 - a; s = -1.0f; }   // cos(pi-x)  = -cos(x)
            t.v[i][j] = s * ck[a];
        }
    }
    return t;
}

// learned quant matrix, produced once per launch by the tiny setup kernel
__device__ float g_lq[64];

__device__ __forceinline__ float gelu_exact(float x) {
    return 0.5f * x * (1.0f + erff(x * 0.70710678f));
}

// ---------------------------------------------------------------------------
// Setup kernel: noise MLP -> nr[18]; softmax(qmat_weights);
// learned_qmat[h][w] = sum_i (softmax_i*nr0 + nr1)*nr[2+i] * qmat[i][h][w].
// ---------------------------------------------------------------------------
__global__ void setup_kernel(const float* __restrict__ noise,
                             const float* __restrict__ qmat,
                             const float* __restrict__ qmw,
                             const float* __restrict__ w1, const float* __restrict__ b1,
                             const float* __restrict__ w2, const float* __restrict__ b2,
                             const float* __restrict__ w3, const float* __restrict__ b3) {
    int t = threadIdx.x;  // 0..63
    float nz = noise[0];

    float h1[16], h2[16];
#pragma unroll
    for (int k = 0; k < 16; k++) h1[k] = gelu_exact(nz * w1[k] + b1[k]);
#pragma unroll
    for (int k = 0; k < 16; k++) {
        float s = b2[k];
#pragma unroll
        for (int j = 0; j < 16; j++) s += h1[j] * w2[j * 16 + k];
        h2[k] = gelu_exact(s);
    }
    float nr[18];
#pragma unroll
    for (int k = 0; k < 18; k++) {
        float s = b3[k];
#pragma unroll
        for (int j = 0; j < 16; j++) s += h2[j] * w3[j * 18 + k];
        nr[k] = s;
    }

    float wmax = qmw[0];
#pragma unroll
    for (int i = 1; i < 16; i++) wmax = fmaxf(wmax, qmw[i]);
    float e[16], esum = 0.0f;
#pragma unroll
    for (int i = 0; i < 16; i++) { e[i] = expf(qmw[i] - wmax); esum += e[i]; }
    float inv = 1.0f / esum;

    float acc = 0.0f;
#pragma unroll
    for (int i = 0; i < 16; i++) {
        float coef = (e[i] * inv * nr[0] + nr[1]) * nr[2 + i];
        acc += coef * qmat[i * 64 + t];
    }
    g_lq[t] = acc;
}

// ---------------------------------------------------------------------------
// Main kernel: ONE THREAD per 8x8 block, whole block in registers.
// No shared-memory transposes: after full unroll, "column" access is just a
// different constant register index. Pipeline per thread:
//   load 64 floats (16 LDG.128, coalesced across the warp)
//   W = rowDCT(x); colDCT in place; W *= q; colIDCT in place; rowIDCT
//   low = W, high = x - low (orthogonality identity), 32 STG.128 out.
// q (64 floats) sits in smem; the mask reads are warp-uniform float4
// broadcasts (16 LDS.128 per thread, 1 wavefront each).
// ---------------------------------------------------------------------------
__global__ void __launch_bounds__(128)
dct_kernel(const float* __restrict__ x,
           float* __restrict__ lo,
           float* __restrict__ hi) {
    constexpr DCTTab CD = make_dct();

    __shared__ float4 sq4[16];
    if (threadIdx.x < 16)
        sq4[threadIdx.x] = reinterpret_cast<const float4*>(g_lq)[threadIdx.x];
    __syncthreads();

    const int b   = blockIdx.x * 128 + threadIdx.x;  // global block id
    const int img = b >> 6;
    const int by  = (b >> 3) & 7;
    const int bx  = b & 7;
    const long base = (long)img * 4096 + by * 512 + bx * 8;  // floats

    // ---- load 8x8 block ----
    float xv[64];
#pragma unroll
    for (int r = 0; r < 8; r++) {
        const float4* p = reinterpret_cast<const float4*>(x + base + r * 64);
        float4 a = p[0], c = p[1];
        xv[r * 8 + 0] = a.x; xv[r * 8 + 1] = a.y; xv[r * 8 + 2] = a.z; xv[r * 8 + 3] = a.w;
        xv[r * 8 + 4] = c.x; xv[r * 8 + 5] = c.y; xv[r * 8 + 6] = c.z; xv[r * 8 + 7] = c.w;
    }

    // ---- row DCT: W[r][m] = sum_j x[r][j] * C[m][j] ----
    float w[64];
#pragma unroll
    for (int r = 0; r < 8; r++) {
#pragma unroll
        for (int m = 0; m < 8; m++) {
            float acc = 0.0f;
#pragma unroll
            for (int j = 0; j < 8; j++) acc = fmaf(xv[r * 8 + j], CD.v[m][j], acc);
            w[r * 8 + m] = acc;
        }
    }

    // ---- col DCT in place: Z[i][c] = sum_r C[i][r] * W[r][c] ----
#pragma unroll
    for (int c = 0; c < 8; c++) {
        float y[8];
#pragma unroll
        for (int r = 0; r < 8; r++) y[r] = w[r * 8 + c];
#pragma unroll
        for (int i = 0; i < 8; i++) {
            float acc = 0.0f;
#pragma unroll
            for (int r = 0; r < 8; r++) acc = fmaf(y[r], CD.v[i][r], acc);
            w[i * 8 + c] = acc;
        }
    }

    // ---- spectral mask: W *= q (warp-uniform float4 smem broadcasts) ----
#pragma unroll
    for (int k = 0; k < 16; k++) {
        float4 q = sq4[k];
        w[k * 4 + 0] *= q.x;
        w[k * 4 + 1] *= q.y;
        w[k * 4 + 2] *= q.z;
        w[k * 4 + 3] *= q.w;
    }

    // ---- col IDCT in place: V[a][c] = sum_i C[i][a] * Z[i][c] ----
#pragma unroll
    for (int c = 0; c < 8; c++) {
        float z[8];
#pragma unroll
        for (int i = 0; i < 8; i++) z[i] = w[i * 8 + c];
#pragma unroll
        for (int a = 0; a < 8; a++) {
            float acc = 0.0f;
#pragma unroll
            for (int i = 0; i < 8; i++) acc = fmaf(z[i], CD.v[i][a], acc);
            w[a * 8 + c] = acc;
        }
    }

    // ---- row IDCT + high = x - low + stores ----
#pragma unroll
    for (int r = 0; r < 8; r++) {
        float t[8];
#pragma unroll
        for (int m = 0; m < 8; m++) t[m] = w[r * 8 + m];

        float lv[8], hv[8];
#pragma unroll
        for (int bb = 0; bb < 8; bb++) {
            float acc = 0.0f;
#pragma unroll
            for (int m = 0; m < 8; m++) acc = fmaf(t[m], CD.v[m][bb], acc);
            lv[bb] = acc;
            hv[bb] = xv[r * 8 + bb] - acc;
        }

        float4* lp = reinterpret_cast<float4*>(lo + base + r * 64);
        lp[0] = make_float4(lv[0], lv[1], lv[2], lv[3]);
        lp[1] = make_float4(lv[4], lv[5], lv[6], lv[7]);
        float4* hp = reinterpret_cast<float4*>(hi + base + r * 64);
        hp[0] = make_float4(hv[0], hv[1], hv[2], hv[3]);
        hp[1] = make_float4(hv[4], hv[5], hv[6], hv[7]);
    }
}

// ---------------------------------------------------------------------------
// Launch: metadata order = x, noise_level, qmat, qmat_weights, w1,b1,w2,b2,w3,b3
// d_out = [low (N floats) | high (N floats)]
// ---------------------------------------------------------------------------
extern "C" void kernel_launch(void* const* d_in, const int* in_sizes, int n_in,
                              void* d_out, int out_size) {
    const float* x     = (const float*)d_in[0];
    const float* noise = (const float*)d_in[1];
    const float* qmat  = (const float*)d_in[2];
    const float* qmw   = (const float*)d_in[3];
    const float* w1    = (const float*)d_in[4];
    const float* b1    = (const float*)d_in[5];
    const float* w2    = (const float*)d_in[6];
    const float* b2    = (const float*)d_in[7];
    const float* w3    = (const float*)d_in[8];
    const float* b3    = (const float*)d_in[9];

    const int N       = in_sizes[0];   // 33554432
    const int nblocks = N / 64;        // 8x8 blocks total (524288)
    const int grid    = nblocks / 128;

    float* lo = (float*)d_out;
    float* hi = lo + N;

    setup_kernel<<<1, 64>>>(noise, qmat, qmw, w1, b1, w2, b2, w3, b3);
    dct_kernel<<<grid, 128>>>(x, lo, hi);
}